// round 3
// baseline (speedup 1.0000x reference)
#include <cuda_runtime.h>
#include <cstdint>

#define Bsz 64
#define Ssz 2048
#define Isz 512
#define Hsz 512

// ============================================================
// Phase 1: xW = x @ W + b   (M=131072, K=512, N=512)
// 128x128 block tile, BK=8, 256 threads, 8x8 thread tile,
// packed f32x2 FMA (2x fp32 rate on sm_103a).
// ============================================================
__global__ __launch_bounds__(256, 1) void sgemm_xw(
    const float* __restrict__ A,    // [M,512] = x
    const float* __restrict__ Wm,   // [512,512] = W_i (row-major [K][N])
    const float* __restrict__ bias, // [512]
    float* __restrict__ C)          // [M,512] = xW+b (hidden region of d_out)
{
    constexpr int K = 512, N = 512;
    __shared__ float As[8][128];
    __shared__ float Bs[8][128];

    const int tid  = threadIdx.x;
    const int bm   = blockIdx.y, bn = blockIdx.x;
    const int arow = tid >> 1, acol = (tid & 1) << 2;   // A tile: 128 rows x 8 k
    const int brow = tid >> 5, bcol = (tid & 31) << 2;  // B tile: 8 k x 128 cols
    const int tx   = tid & 15, ty = tid >> 4;           // 8x8 thread tile

    const float* Ab = A + (size_t)bm * 128 * K;
    const float* Bb = Wm + bn * 128;

    unsigned long long acc[8][4];
#pragma unroll
    for (int i = 0; i < 8; i++)
#pragma unroll
        for (int j = 0; j < 4; j++) acc[i][j] = 0ull;

    for (int kk = 0; kk < K; kk += 8) {
        float4 av = *(const float4*)(Ab + (size_t)arow * K + kk + acol);
        float4 bv = *(const float4*)(Bb + (size_t)(kk + brow) * N + bcol);
        __syncthreads();   // previous compute done before smem overwrite
        As[acol + 0][arow] = av.x;
        As[acol + 1][arow] = av.y;
        As[acol + 2][arow] = av.z;
        As[acol + 3][arow] = av.w;
        *(float4*)&Bs[brow][bcol] = bv;
        __syncthreads();
#pragma unroll
        for (int k = 0; k < 8; k++) {
            float4 a0 = *(const float4*)&As[k][ty * 8];
            float4 a1 = *(const float4*)&As[k][ty * 8 + 4];
            ulonglong2 b0 = *(const ulonglong2*)&Bs[k][tx * 8];
            ulonglong2 b1 = *(const ulonglong2*)&Bs[k][tx * 8 + 4];
            float ar[8] = {a0.x, a0.y, a0.z, a0.w, a1.x, a1.y, a1.z, a1.w};
            unsigned long long br[4] = {b0.x, b0.y, b1.x, b1.y};
#pragma unroll
            for (int i = 0; i < 8; i++) {
                unsigned long long ad;
                unsigned int au = __float_as_uint(ar[i]);
                asm("mov.b64 %0, {%1, %1};" : "=l"(ad) : "r"(au));
#pragma unroll
                for (int j = 0; j < 4; j++)
                    asm("fma.rn.f32x2 %0, %1, %2, %0;"
                        : "+l"(acc[i][j]) : "l"(ad), "l"(br[j]));
            }
        }
    }

    // bias add + store (8B-aligned packed stores)
    const int cb = bn * 128 + tx * 8;
    ulonglong2 bb0 = *(const ulonglong2*)&bias[cb];
    ulonglong2 bb1 = *(const ulonglong2*)&bias[cb + 4];
    unsigned long long bz[4] = {bb0.x, bb0.y, bb1.x, bb1.y};
#pragma unroll
    for (int i = 0; i < 8; i++) {
        size_t row = (size_t)bm * 128 + ty * 8 + i;
        float* Crow = C + row * N + cb;
#pragma unroll
        for (int j = 0; j < 4; j++) {
            unsigned long long v;
            asm("add.rn.f32x2 %0, %1, %2;" : "=l"(v) : "l"(acc[i][j]), "l"(bz[j]));
            *(unsigned long long*)(Crow + 2 * j) = v;
        }
    }
}

// ============================================================
// Phase 2: persistent cluster RNN scan.
// 16 clusters x 8 CTAs (grid 128), 256 threads/CTA.
// Cluster handles 4 batch rows; CTA rank r owns U columns [64r,64r+64),
// held entirely in registers (4-way K-split x 64 cols x 128 regs).
// h lives in a double-buffered smem array, exchanged each step via
// DSMEM stores + one cluster barrier. hidden[] is read (xw) and
// overwritten (h) in place.
// ============================================================
__global__ void __launch_bounds__(256, 1) __cluster_dims__(8, 1, 1)
rnn_scan(const float* __restrict__ U,      // [512,512] row-major [k][h]
         float* __restrict__ hidden,       // [B,S,H]: in = xW+b, out = h
         float* __restrict__ hlast)        // [B,H]
{
    __shared__ float hbuf[2][512][4];      // [buf][k][batch]
    __shared__ float red[4][64][4];        // [ksplit][col][batch]

    const int tid = threadIdx.x;
    unsigned int rank;
    asm("mov.u32 %0, %%cluster_ctarank;" : "=r"(rank));
    const int cid = blockIdx.x >> 3;       // cluster id 0..15
    const int b0  = cid * 4;               // 4 batches per cluster
    const int ks  = tid >> 6;              // K split 0..3 (128 k each)
    const int c   = tid & 63;              // local column
    const int cg  = (int)rank * 64 + c;    // global column 0..511

    // One-time: pull this thread's U column-chunk into registers.
    float Ureg[128];
#pragma unroll
    for (int j = 0; j < 128; j++)
        Ureg[j] = U[(size_t)(ks * 128 + j) * Hsz + cg];

    // h0 = 0
    {
        float* hz = &hbuf[0][0][0];
        for (int i = tid; i < 2 * 512 * 4; i += 256) hz[i] = 0.0f;
    }
    __syncthreads();
    asm volatile("barrier.cluster.arrive.aligned;" ::: "memory");
    asm volatile("barrier.cluster.wait.aligned;" ::: "memory");

    const unsigned int laddr0 =
        (unsigned int)__cvta_generic_to_shared(&hbuf[0][cg][0]);
    const unsigned int laddr1 =
        (unsigned int)__cvta_generic_to_shared(&hbuf[1][cg][0]);

    for (int t = 0; t < Ssz; t++) {
        const int p = t & 1;

        // Prefetch xw for this step's epilogue (writer threads only).
        float xw0 = 0.f, xw1 = 0.f, xw2 = 0.f, xw3 = 0.f;
        size_t base = 0;
        if (tid < 64) {
            base = ((size_t)b0 * Ssz + t) * Hsz + (size_t)rank * 64 + tid;
            xw0 = __ldg(hidden + base);
            xw1 = __ldg(hidden + base + (size_t)Ssz * Hsz);
            xw2 = __ldg(hidden + base + 2 * (size_t)Ssz * Hsz);
            xw3 = __ldg(hidden + base + 3 * (size_t)Ssz * Hsz);
        }

        // Partial dot products: 4 batches x 1 column x 128 k, packed f32x2.
        const ulonglong2* hk = ((const ulonglong2*)hbuf[p]) + ks * 128;
        unsigned long long a01a = 0ull, a01b = 0ull, a23a = 0ull, a23b = 0ull;
#pragma unroll
        for (int j = 0; j < 128; j += 2) {
            ulonglong2 h0 = hk[j];
            ulonglong2 h1 = hk[j + 1];
            unsigned long long u0, u1;
            unsigned int uu0 = __float_as_uint(Ureg[j]);
            unsigned int uu1 = __float_as_uint(Ureg[j + 1]);
            asm("mov.b64 %0, {%1, %1};" : "=l"(u0) : "r"(uu0));
            asm("mov.b64 %0, {%1, %1};" : "=l"(u1) : "r"(uu1));
            asm("fma.rn.f32x2 %0, %1, %2, %0;" : "+l"(a01a) : "l"(u0), "l"(h0.x));
            asm("fma.rn.f32x2 %0, %1, %2, %0;" : "+l"(a23a) : "l"(u0), "l"(h0.y));
            asm("fma.rn.f32x2 %0, %1, %2, %0;" : "+l"(a01b) : "l"(u1), "l"(h1.x));
            asm("fma.rn.f32x2 %0, %1, %2, %0;" : "+l"(a23b) : "l"(u1), "l"(h1.y));
        }
        unsigned long long a01, a23;
        asm("add.rn.f32x2 %0, %1, %2;" : "=l"(a01) : "l"(a01a), "l"(a01b));
        asm("add.rn.f32x2 %0, %1, %2;" : "=l"(a23) : "l"(a23a), "l"(a23b));
        unsigned int w0, w1, w2, w3;
        asm("mov.b64 {%0, %1}, %2;" : "=r"(w0), "=r"(w1) : "l"(a01));
        asm("mov.b64 {%0, %1}, %2;" : "=r"(w2), "=r"(w3) : "l"(a23));
        *(float4*)&red[ks][c][0] =
            make_float4(__uint_as_float(w0), __uint_as_float(w1),
                        __uint_as_float(w2), __uint_as_float(w3));
        __syncthreads();

        if (tid < 64) {
            float4 r0 = *(const float4*)&red[0][tid][0];
            float4 r1 = *(const float4*)&red[1][tid][0];
            float4 r2 = *(const float4*)&red[2][tid][0];
            float4 r3 = *(const float4*)&red[3][tid][0];
            float v0 = tanhf(xw0 + r0.x + r1.x + r2.x + r3.x);
            float v1 = tanhf(xw1 + r0.y + r1.y + r2.y + r3.y);
            float v2 = tanhf(xw2 + r0.z + r1.z + r2.z + r3.z);
            float v3 = tanhf(xw3 + r0.w + r1.w + r2.w + r3.w);

            // Emit hidden state (overwrites xw slot in place).
            hidden[base]                          = v0;
            hidden[base + (size_t)Ssz * Hsz]      = v1;
            hidden[base + 2 * (size_t)Ssz * Hsz]  = v2;
            hidden[base + 3 * (size_t)Ssz * Hsz]  = v3;
            if (t == Ssz - 1) {
                const size_t lb = (size_t)b0 * Hsz + (size_t)rank * 64 + tid;
                hlast[lb]            = v0;
                hlast[lb + Hsz]      = v1;
                hlast[lb + 2 * Hsz]  = v2;
                hlast[lb + 3 * Hsz]  = v3;
            }

            // Broadcast this column's 4 batch values into hbuf[p^1] of all
            // 8 cluster CTAs (including self) via DSMEM.
            const unsigned int la = p ? laddr0 : laddr1;  // buffer p^1
#pragma unroll
            for (int r = 0; r < 8; r++) {
                unsigned int ra;
                asm("mapa.shared::cluster.u32 %0, %1, %2;"
                    : "=r"(ra) : "r"(la), "r"(r));
                asm volatile("st.shared::cluster.v4.f32 [%0], {%1,%2,%3,%4};"
                             :: "r"(ra), "f"(v0), "f"(v1), "f"(v2), "f"(v3)
                             : "memory");
            }
        }

        // One cluster barrier per step: releases our DSMEM writes,
        // acquires peers' writes into hbuf[p^1].
        asm volatile("barrier.cluster.arrive.aligned;" ::: "memory");
        asm volatile("barrier.cluster.wait.aligned;" ::: "memory");
    }
}

extern "C" void kernel_launch(void* const* d_in, const int* in_sizes, int n_in,
                              void* d_out, int out_size) {
    const float* x  = (const float*)d_in[0];   // [64,2048,512]
    const float* Wi = (const float*)d_in[1];   // [512,512]
    const float* Ui = (const float*)d_in[2];   // [512,512]
    const float* bi = (const float*)d_in[3];   // [512]

    float* hidden = (float*)d_out;                                   // [B,S,H]
    float* hlast  = hidden + (size_t)Bsz * Ssz * Hsz;                 // [B,H]

    // Phase 1: xW + b -> hidden (in place staging)
    dim3 g1(Hsz / 128, (Bsz * Ssz) / 128);   // (4, 1024)
    sgemm_xw<<<g1, 256>>>(x, Wi, bi, hidden);

    // Phase 2: sequential scan, persistent cluster kernel.
    rnn_scan<<<128, 256>>>(Ui, hidden, hlast);
}